// round 15
// baseline (speedup 1.0000x reference)
#include <cuda_runtime.h>
#include <cuda_fp16.h>
#include <cstdint>

#define NN 20000
#define EE 640000
#define HH 128
#define TE 128          // edges per tile
#define TPB 4           // tiles per edge block
#define NT 256
#define TN 64           // nodes per block (node/proj kernels)

// Scratch state (device globals: no allocation allowed)
__device__ float g_h[NN * HH];
__device__ float g_x[NN * 3];
__device__ float g_m[NN * HH];      // per-layer: Σ_edges C1 (then @eW2 in node)
__device__ float g_xacc[NN * 3];
__device__ float g_p1[NN * HH];     // h @ eW1[0:128]
__device__ float g_p2[NN * HH];     // h @ eW1[128:256]
__device__ float g_deg[NN];         // edge out-degree
__device__ float g_vb[128];         // eb2 @ cW1 + cb1
// fp16-packed transposed weights, chunk-major [4][128n][16kpair] uint32 each:
// 0=eW1a 1=eW1b 2=eW2 3=cW1(unused) 4=nW1a 5=nW1b 6=nW2 7=Mc(eW2@cW1)
__device__ uint32_t g_wp[8 * 8192];

// ===========================================================================
// helpers
// ===========================================================================
__device__ __forceinline__ uint32_t pack_h2(float a, float b) {
    __half2 h = __floats2half2_rn(a, b);
    return *(uint32_t*)&h;
}

__device__ __forceinline__ void mma16h(float* c,
                                       uint32_t a0, uint32_t a1, uint32_t a2, uint32_t a3,
                                       uint32_t b0, uint32_t b1) {
    asm volatile(
        "mma.sync.aligned.m16n8k16.row.col.f32.f16.f16.f32 "
        "{%0,%1,%2,%3}, {%4,%5,%6,%7}, {%8,%9}, {%0,%1,%2,%3};"
        : "+f"(c[0]), "+f"(c[1]), "+f"(c[2]), "+f"(c[3])
        : "r"(a0), "r"(a1), "r"(a2), "r"(a3), "r"(b0), "r"(b1));
}

__device__ __forceinline__ void red_v4(float* p, float a, float b, float c, float d) {
    asm volatile("red.global.add.v4.f32 [%0], {%1,%2,%3,%4};"
                 :: "l"(p), "f"(a), "f"(b), "f"(c), "f"(d) : "memory");
}

// ===========================================================================
// smem layouts (uint32 indices)
// ===========================================================================
#define PAH 68
// W buffer: full 128x128 fp16 tile = 8192 u32, XOR-swizzled:
//   u32 index of (chunk, n, kp) = chunk*2048 + n*16 + (kp ^ (((n>>1)&3)<<2))
// edge kernel (TE=128)
#define S_ACOL 0                          // 8704 (C1)
#define S_WBUF (S_ACOL + TE * PAH)        // 8192 (Mc, staged once per block)
#define S_EB1  (S_WBUF + 8192)            // 128 (floats)
#define S_W1L  (S_EB1 + 128)
#define S_VB   (S_W1L + 128)
#define S_CW2  (S_VB + 128)
#define S_SROW (S_CW2 + 128)              // int[128]
#define S_SCOL (S_SROW + TE)
#define S_SREL (S_SCOL + TE)              // 128*3 floats
#define S_SRD  (S_SREL + TE * 3)          // 128
#define S_PART (S_SRD + TE)               // 128*2
#define S_TOT  (S_PART + TE * 2)
#define EDGE_SMEM_BYTES (S_TOT * 4)       // 73728 B -> 3 CTAs/SM
// node / proj kernels (TN=64)
#define N_AH   0
#define N_AM   (N_AH + TN * PAH)
#define N_WBUF (N_AM + TN * PAH)
#define N_B1   (N_WBUF + 8192)
#define N_B2   (N_B1 + 128)
#define N_EB2  (N_B2 + 128)
#define N_TOT  (N_EB2 + 128)
#define NODE_SMEM_BYTES (N_TOT * 4)
#define P_AH   0
#define P_WBUF (P_AH + TN * PAH)
#define PROJ_SMEM_BYTES ((P_WBUF + 8192) * 4)

// stage full 128x128 W tile into swizzled smem (2048 uint4s, 8/thread)
__device__ __forceinline__ void stage_w(const uint32_t* __restrict__ Wg,
                                        uint32_t* __restrict__ Wbuf, int tid)
{
    __syncthreads();
#pragma unroll
    for (int i = 0; i < 8; i++) {
        int j = tid + 256 * i;
        int chunk = j >> 9;
        int n = (j >> 2) & 127;
        int kq = j & 3;
        *(uint4*)&Wbuf[chunk * 2048 + n * 16 + 4 * (kq ^ ((n >> 1) & 3))] =
            ((const uint4*)Wg)[j];
    }
    __syncthreads();
}

// MMA-only edge pass (W already resident): acc[2][8][4] += As @ W (32x64 warp)
__device__ __forceinline__ void gemm_mma_e(const uint32_t* __restrict__ As,
                                           const uint32_t* __restrict__ Wbuf,
                                           float acc[2][8][4],
                                           int lane, int m_base, int n_base)
{
    const int g = lane >> 2, t = lane & 3;
    const int s = ((g >> 1) & 3) << 2;

#pragma unroll
    for (int ch = 0; ch < 4; ch++) {
        const uint32_t* Wc = Wbuf + ch * 2048;
#pragma unroll
        for (int ks = 0; ks < 2; ks++) {
            const int kp = ch * 16 + ks * 8;
            const uint32_t* A0 = As + (m_base + g) * PAH + kp + t;
            uint32_t a00 = A0[0], a01 = A0[8 * PAH], a02 = A0[4], a03 = A0[8 * PAH + 4];
            const uint32_t* A1 = A0 + 16 * PAH;
            uint32_t a10 = A1[0], a11 = A1[8 * PAH], a12 = A1[4], a13 = A1[8 * PAH + 4];
            const int kb = ks * 8;
#pragma unroll
            for (int nt = 0; nt < 8; nt++) {
                const uint32_t* Bb = Wc + (n_base + nt * 8 + g) * 16;
                uint32_t b0 = Bb[(kb + t) ^ s];
                uint32_t b1 = Bb[(kb + t + 4) ^ s];
                mma16h(acc[0][nt], a00, a01, a02, a03, b0, b1);
                mma16h(acc[1][nt], a10, a11, a12, a13, b0, b1);
            }
        }
    }
}

__device__ __forceinline__ void zacc_e(float acc[2][8][4]) {
#pragma unroll
    for (int m = 0; m < 2; m++)
#pragma unroll
        for (int n = 0; n < 8; n++)
#pragma unroll
            for (int j = 0; j < 4; j++) acc[m][n][j] = 0.0f;
}

// node-side pass (warp tile 32x32, stages W per call)
__device__ __forceinline__ void gemm_pass_h(const uint32_t* __restrict__ As,
                                            const uint32_t* __restrict__ Wg,
                                            uint32_t* __restrict__ Wbuf,
                                            float acc[2][4][4],
                                            int tid, int lane, int m_base, int n_base)
{
    const int g = lane >> 2, t = lane & 3;
    const int s = ((g >> 1) & 3) << 2;

    stage_w(Wg, Wbuf, tid);

#pragma unroll
    for (int ch = 0; ch < 4; ch++) {
        const uint32_t* Wc = Wbuf + ch * 2048;
#pragma unroll
        for (int ks = 0; ks < 2; ks++) {
            const int kp = ch * 16 + ks * 8;
            const uint32_t* A0 = As + (m_base + g) * PAH + kp + t;
            uint32_t a00 = A0[0], a01 = A0[8 * PAH], a02 = A0[4], a03 = A0[8 * PAH + 4];
            const uint32_t* A1 = A0 + 16 * PAH;
            uint32_t a10 = A1[0], a11 = A1[8 * PAH], a12 = A1[4], a13 = A1[8 * PAH + 4];
            const int kb = ks * 8;
#pragma unroll
            for (int nt = 0; nt < 4; nt++) {
                const uint32_t* Bb = Wc + (n_base + nt * 8 + g) * 16;
                uint32_t b0 = Bb[(kb + t) ^ s];
                uint32_t b1 = Bb[(kb + t + 4) ^ s];
                mma16h(acc[0][nt], a00, a01, a02, a03, b0, b1);
                mma16h(acc[1][nt], a10, a11, a12, a13, b0, b1);
            }
        }
    }
}

__device__ __forceinline__ void zacc(float acc[2][4][4]) {
#pragma unroll
    for (int m = 0; m < 2; m++)
#pragma unroll
        for (int n = 0; n < 4; n++)
#pragma unroll
            for (int j = 0; j < 4; j++) acc[m][n][j] = 0.0f;
}

// prep: fp16-pack weight tiles, transposed [n][k], chunk-major
__global__ void prep_kernel(const float* __restrict__ eW1,
                            const float* __restrict__ eW2,
                            const float* __restrict__ cW1,
                            const float* __restrict__ nW1,
                            const float* __restrict__ nW2)
{
    int idx = blockIdx.x * blockDim.x + threadIdx.x;
    if (idx >= 7 * 8192) return;
    int mat = idx >> 13;
    int rem = idx & 8191;
    int chunk = rem >> 11;
    int n = (rem >> 4) & 127;
    int kp = rem & 15;
    int k = chunk * 32 + kp * 2;
    const float* W;
    int off = 0;
    switch (mat) {
        case 0: W = eW1; break;
        case 1: W = eW1; off = 128 * 128; break;
        case 2: W = eW2; break;
        case 3: W = cW1; break;
        case 4: W = nW1; break;
        case 5: W = nW1; off = 128 * 128; break;
        default: W = nW2; break;
    }
    g_wp[idx] = pack_h2(W[off + k * 128 + n], W[off + (k + 1) * 128 + n]);
}

// compose: Mc = eW2 @ cW1 (coalesced: n fastest); vb = eb2@cW1 + cb1
__global__ void compose_kernel(const float* __restrict__ eW2,
                               const float* __restrict__ cW1,
                               const float* __restrict__ eb2,
                               const float* __restrict__ cb1)
{
    int idx = blockIdx.x * blockDim.x + threadIdx.x;
    if (idx < 8192) {
        int n = idx & 127;                // fastest -> cW1 reads coalesced
        int kp = (idx >> 7) & 15;
        int chunk = idx >> 11;
        int k = chunk * 32 + kp * 2;
        float s0 = 0.0f, s1 = 0.0f;
        for (int j = 0; j < 128; j++) {
            float c = cW1[j * 128 + n];
            s0 = fmaf(eW2[k * 128 + j], c, s0);
            s1 = fmaf(eW2[(k + 1) * 128 + j], c, s1);
        }
        g_wp[7 * 8192 + chunk * 2048 + n * 16 + kp] = pack_h2(s0, s1);
    }
    if (idx < 128) {
        float s = cb1[idx];
        for (int j = 0; j < 128; j++)
            s = fmaf(eb2[j], cW1[j * 128 + idx], s);
        g_vb[idx] = s;
    }
    if (idx >= 8192 && idx - 8192 < NN) g_deg[idx - 8192] = 0.0f;
}

__global__ void deg_kernel(const int* __restrict__ ei) {
    int e = blockIdx.x * blockDim.x + threadIdx.x;
    if (e < EE) {
        int r = ei[e];
        if ((unsigned)r >= NN) r = 0;
        atomicAdd(&g_deg[r], 1.0f);
    }
}

// proj: P1 = h @ eW1a, P2 = h @ eW1b  (fp32 out)
__global__ void __launch_bounds__(NT, 3) proj_kernel()
{
    extern __shared__ uint32_t smu[];
    uint32_t* AH   = smu + P_AH;
    uint32_t* Wbuf = smu + P_WBUF;

    const int tid  = threadIdx.x;
    const int lane = tid & 31;
    const int wid  = tid >> 5;
    const int m_base = (wid & 1) * 32;
    const int n_base = (wid >> 1) * 32;
    const int g = lane >> 2, t = lane & 3;
    const int n0 = blockIdx.x * TN;

    for (int j = tid; j < TN * 32; j += NT) {
        int e = j >> 5, c4 = j & 31;
        int n = n0 + e; if (n >= NN) n = NN - 1;
        float4 hv = ((const float4*)(g_h + (size_t)n * HH))[c4];
        *(uint2*)&AH[e * PAH + c4 * 2] =
            make_uint2(pack_h2(hv.x, hv.y), pack_h2(hv.z, hv.w));
    }

    float acc[2][4][4];

#pragma unroll
    for (int pp = 0; pp < 2; pp++) {
        float* dst = pp ? g_p2 : g_p1;
        zacc(acc);
        gemm_pass_h(AH, g_wp + pp * 8192, Wbuf, acc, tid, lane, m_base, n_base);
#pragma unroll
        for (int m = 0; m < 2; m++)
#pragma unroll
            for (int half = 0; half < 2; half++) {
                const int r = m_base + m * 16 + g + half * 8;
                const int n = n0 + r;
                if (n < NN) {
#pragma unroll
                    for (int nt = 0; nt < 4; nt++) {
                        int c = n_base + nt * 8 + t * 2;
                        dst[(size_t)n * HH + c]     = acc[m][nt][half * 2 + 0];
                        dst[(size_t)n * HH + c + 1] = acc[m][nt][half * 2 + 1];
                    }
                }
            }
    }
}

// ---------------------------------------------------------------------------
// Fused edge pass. 4 tiles/block, Mc staged once, 3 CTAs/SM.
//   C1 = relu(P1[row]+P2[col]+rd*w1l+eb1)  -> red.v4 into g_m + fp16 smem
//   alpha = relu(C1 @ Mc + vb) . cW2 + cb2 -> scatter alpha*rel into g_xacc
// ---------------------------------------------------------------------------
__global__ void __launch_bounds__(NT, 3) edge_kernel(
    const int* __restrict__ ei,
    const float* __restrict__ eb1, const float* __restrict__ cW2,
    const float* __restrict__ cb2, const float* __restrict__ eW1)
{
    extern __shared__ uint32_t smu[];
    float* smf = (float*)smu;
    uint32_t* Acol = smu + S_ACOL;      // C1
    uint32_t* Wbuf = smu + S_WBUF;      // Mc, resident for whole block
    int*   srow = (int*)(smu + S_SROW);
    int*   scol = (int*)(smu + S_SCOL);
    float* srel = smf + S_SREL;
    float* srd  = smf + S_SRD;
    float* spart= smf + S_PART;

    const int tid  = threadIdx.x;
    const int lane = tid & 31;
    const int wid  = tid >> 5;
    const int m_base = (wid & 3) * 32;
    const int n_base = (wid >> 2) * 64;
    const int wn = wid >> 2;
    const int g = lane >> 2, t = lane & 3;

    // stage Mc once per block
#pragma unroll
    for (int i = 0; i < 8; i++) {
        int j = tid + 256 * i;
        int chunk = j >> 9;
        int n = (j >> 2) & 127;
        int kq = j & 3;
        *(uint4*)&Wbuf[chunk * 2048 + n * 16 + 4 * (kq ^ ((n >> 1) & 3))] =
            ((const uint4*)(g_wp + 7 * 8192))[j];
    }
    if (tid < 128) {
        smf[S_EB1 + tid] = eb1[tid];
        smf[S_VB  + tid] = g_vb[tid];
        smf[S_CW2 + tid] = cW2[tid];
        smf[S_W1L + tid] = eW1[256 * 128 + tid];
    }
    const float cb2v = cb2[0];

    for (int it = 0; it < TPB; it++) {
        const int e0 = (blockIdx.x * TPB + it) * TE;
        __syncthreads();                // staging (it=0) / prev alpha scatter done

        if (tid < TE) {
            int e = e0 + tid;
            int r = ei[e];
            int c = ei[EE + e];
            if ((unsigned)r >= NN) r = 0;
            if ((unsigned)c >= NN) c = 0;
            srow[tid] = r;
            scol[tid] = c;
            float dx = g_x[r * 3 + 0] - g_x[c * 3 + 0];
            float dy = g_x[r * 3 + 1] - g_x[c * 3 + 1];
            float dz = g_x[r * 3 + 2] - g_x[c * 3 + 2];
            srel[tid * 3 + 0] = dx; srel[tid * 3 + 1] = dy; srel[tid * 3 + 2] = dz;
            srd[tid] = dx * dx + dy * dy + dz * dz;
        }
        __syncthreads();                // indices + srd ready

        // fused gather + C1 epilogue + C1 scatter (m-path)
        for (int j = tid; j < TE * 32; j += NT) {
            int e = j >> 5, c4 = j & 31;
            int c = c4 * 4;
            float4 p1 = ((const float4*)(g_p1 + (size_t)srow[e] * HH))[c4];
            float4 p2 = ((const float4*)(g_p2 + (size_t)scol[e] * HH))[c4];
            float rd = srd[e];
            float v0 = fmaxf(p1.x + p2.x + rd * smf[S_W1L + c]     + smf[S_EB1 + c],     0.0f);
            float v1 = fmaxf(p1.y + p2.y + rd * smf[S_W1L + c + 1] + smf[S_EB1 + c + 1], 0.0f);
            float v2 = fmaxf(p1.z + p2.z + rd * smf[S_W1L + c + 2] + smf[S_EB1 + c + 2], 0.0f);
            float v3 = fmaxf(p1.w + p2.w + rd * smf[S_W1L + c + 3] + smf[S_EB1 + c + 3], 0.0f);
            red_v4(&g_m[(size_t)srow[e] * HH + c], v0, v1, v2, v3);
            *(uint2*)&Acol[e * PAH + c4 * 2] = make_uint2(pack_h2(v0, v1), pack_h2(v2, v3));
        }
        __syncthreads();                // C1 tile ready

        float acc[2][8][4];
        zacc_e(acc);
        gemm_mma_e(Acol, Wbuf, acc, lane, m_base, n_base);

        // alpha epilogue: C3 = relu(acc + vb); alpha = C3 . cW2 + cb2
#pragma unroll
        for (int m = 0; m < 2; m++) {
            const int r0 = m_base + m * 16 + g;
            float p0 = 0.0f, p1 = 0.0f;
#pragma unroll
            for (int nt = 0; nt < 8; nt++) {
                int c = n_base + nt * 8 + t * 2;
                float bA = smf[S_VB + c], bB = smf[S_VB + c + 1];
                float wA = smf[S_CW2 + c], wB = smf[S_CW2 + c + 1];
                p0 = fmaf(fmaxf(acc[m][nt][0] + bA, 0.0f), wA, p0);
                p0 = fmaf(fmaxf(acc[m][nt][1] + bB, 0.0f), wB, p0);
                p1 = fmaf(fmaxf(acc[m][nt][2] + bA, 0.0f), wA, p1);
                p1 = fmaf(fmaxf(acc[m][nt][3] + bB, 0.0f), wB, p1);
            }
            p0 += __shfl_xor_sync(0xffffffffu, p0, 1);
            p0 += __shfl_xor_sync(0xffffffffu, p0, 2);
            p1 += __shfl_xor_sync(0xffffffffu, p1, 1);
            p1 += __shfl_xor_sync(0xffffffffu, p1, 2);
            if (t == 0) {
                spart[r0 * 2 + wn]       = p0;
                spart[(r0 + 8) * 2 + wn] = p1;
            }
        }
        __syncthreads();

        if (tid < TE) {
            float alpha = spart[tid * 2] + spart[tid * 2 + 1] + cb2v;
            int node = srow[tid];
            atomicAdd(&g_xacc[node * 3 + 0], alpha * srel[tid * 3 + 0]);
            atomicAdd(&g_xacc[node * 3 + 1], alpha * srel[tid * 3 + 1]);
            atomicAdd(&g_xacc[node * 3 + 2], alpha * srel[tid * 3 + 2]);
        }
    }
}

// ---------------------------------------------------------------------------
// Node update: m = mc@eW2 + deg*eb2;
//              h += relu([h,m]@nW1+nb1)@nW2+nb2; x += xacc
// ---------------------------------------------------------------------------
__global__ void __launch_bounds__(NT, 3) node_kernel(
    const float* __restrict__ nb1, const float* __restrict__ nb2,
    const float* __restrict__ eb2,
    float* __restrict__ out_h, float* __restrict__ out_x)
{
    extern __shared__ uint32_t smu[];
    float* smf = (float*)smu;
    uint32_t* AH   = smu + N_AH;        // h fp16; reused as C1
    uint32_t* AM   = smu + N_AM;        // mc fp16 -> m fp16
    uint32_t* Wbuf = smu + N_WBUF;

    const int tid  = threadIdx.x;
    const int lane = tid & 31;
    const int wid  = tid >> 5;
    const int m_base = (wid & 1) * 32;
    const int n_base = (wid >> 1) * 32;
    const int g = lane >> 2, t = lane & 3;
    const int n0 = blockIdx.x * TN;

    if (tid < 128) {
        smf[N_B1 + tid] = nb1[tid];
        smf[N_B2 + tid] = nb2[tid];
        smf[N_EB2 + tid] = eb2[tid];
    }

    for (int j = tid; j < TN * 32; j += NT) {
        int e = j >> 5, c4 = j & 31;
        int n = n0 + e; if (n >= NN) n = NN - 1;
        float4 hv = ((const float4*)(g_h + (size_t)n * HH))[c4];
        float4 mv = ((const float4*)(g_m + (size_t)n * HH))[c4];
        *(uint2*)&AH[e * PAH + c4 * 2] =
            make_uint2(pack_h2(hv.x, hv.y), pack_h2(hv.z, hv.w));
        *(uint2*)&AM[e * PAH + c4 * 2] =
            make_uint2(pack_h2(mv.x, mv.y), pack_h2(mv.z, mv.w));
    }

    float acc[2][4][4];

    // ---- m-GEMM: m = mc @ eW2 + deg*eb2 ----
    zacc(acc);
    gemm_pass_h(AM, g_wp + 2 * 8192, Wbuf, acc, tid, lane, m_base, n_base);
    __syncthreads();        // all warps done reading AM before overwrite
#pragma unroll
    for (int m = 0; m < 2; m++) {
        const int r0 = m_base + m * 16 + g, r1 = r0 + 8;
        int na = n0 + r0, nb = n0 + r1;
        float da = (na < NN) ? g_deg[na] : 0.0f;
        float db = (nb < NN) ? g_deg[nb] : 0.0f;
#pragma unroll
        for (int nt = 0; nt < 4; nt++) {
            int c = n_base + nt * 8 + t * 2;
            float eA = smf[N_EB2 + c], eB = smf[N_EB2 + c + 1];
            AM[r0 * PAH + (c >> 1)] = pack_h2(acc[m][nt][0] + da * eA,
                                              acc[m][nt][1] + da * eB);
            AM[r1 * PAH + (c >> 1)] = pack_h2(acc[m][nt][2] + db * eA,
                                              acc[m][nt][3] + db * eB);
        }
    }

    // GEMM1: [h|m] @ nW1  (stage_w's leading sync orders AM writes)
    zacc(acc);
    gemm_pass_h(AH, g_wp + 4 * 8192, Wbuf, acc, tid, lane, m_base, n_base);
    gemm_pass_h(AM, g_wp + 5 * 8192, Wbuf, acc, tid, lane, m_base, n_base);
    __syncthreads();        // all warps done reading AH before C1 overwrite

    // epilogue 1: relu(+nb1) -> fp16 into AH (reused as C1)
#pragma unroll
    for (int m = 0; m < 2; m++) {
        const int r0 = m_base + m * 16 + g, r1 = r0 + 8;
#pragma unroll
        for (int nt = 0; nt < 4; nt++) {
            int c = n_base + nt * 8 + t * 2;
            float bA = smf[N_B1 + c], bB = smf[N_B1 + c + 1];
            AH[r0 * PAH + (c >> 1)] = pack_h2(fmaxf(acc[m][nt][0] + bA, 0.0f),
                                              fmaxf(acc[m][nt][1] + bB, 0.0f));
            AH[r1 * PAH + (c >> 1)] = pack_h2(fmaxf(acc[m][nt][2] + bA, 0.0f),
                                              fmaxf(acc[m][nt][3] + bB, 0.0f));
        }
    }

    // GEMM2: C1 @ nW2
    zacc(acc);
    gemm_pass_h(AH, g_wp + 6 * 8192, Wbuf, acc, tid, lane, m_base, n_base);

    // epilogue 2: h_new = h_old + acc + nb2 -> g_h (+ out)
#pragma unroll
    for (int m = 0; m < 2; m++) {
#pragma unroll
        for (int half = 0; half < 2; half++) {
            const int r = m_base + m * 16 + g + half * 8;
            const int n = n0 + r;
            if (n < NN) {
#pragma unroll
                for (int nt = 0; nt < 4; nt++) {
                    int c = n_base + nt * 8 + t * 2;
                    float a0 = acc[m][nt][half * 2 + 0];
                    float a1 = acc[m][nt][half * 2 + 1];
                    float h0 = g_h[(size_t)n * HH + c]     + a0 + smf[N_B2 + c];
                    float h1 = g_h[(size_t)n * HH + c + 1] + a1 + smf[N_B2 + c + 1];
                    g_h[(size_t)n * HH + c]     = h0;
                    g_h[(size_t)n * HH + c + 1] = h1;
                    if (out_h) {
                        out_h[(size_t)n * HH + c]     = h0;
                        out_h[(size_t)n * HH + c + 1] = h1;
                    }
                }
            }
        }
    }

    for (int tt = tid; tt < TN * 3; tt += NT) {
        int n = n0 + tt / 3;
        if (n < NN) {
            int d = tt % 3;
            float xv = g_x[n * 3 + d] + g_xacc[n * 3 + d];
            g_x[n * 3 + d] = xv;
            if (out_x) out_x[n * 3 + d] = xv;
        }
    }
}

// ===========================================================================
// small setup kernels
// ===========================================================================
__global__ void embed_kernel(const float* __restrict__ hin,
                             const float* __restrict__ W,
                             const float* __restrict__ b)
{
    int j = blockIdx.x * blockDim.x + threadIdx.x;
    if (j >= NN * HH) return;
    int n = j >> 7, c = j & 127;
    float acc = b[c];
#pragma unroll
    for (int k = 0; k < 16; k++)
        acc = fmaf(hin[n * 16 + k], W[k * 128 + c], acc);
    g_h[j] = acc;
}

__global__ void xcopy_kernel(const float* __restrict__ xin)
{
    int i = blockIdx.x * blockDim.x + threadIdx.x;
    if (i < NN * 3) g_x[i] = xin[i];
}

__global__ void zero_kernel()
{
    int i = blockIdx.x * blockDim.x + threadIdx.x;
    if (i < NN * HH / 4) ((float4*)g_m)[i] = make_float4(0.f, 0.f, 0.f, 0.f);
    if (i < NN * 3 / 4) ((float4*)g_xacc)[i] = make_float4(0.f, 0.f, 0.f, 0.f);
}

extern "C" void kernel_launch(void* const* d_in, const int* in_sizes, int n_in,
                              void* d_out, int out_size)
{
    const float* h_in  = (const float*)d_in[0];
    const float* x_in  = (const float*)d_in[1];
    const int*   ei    = (const int*)d_in[2];
    const float* emb_W = (const float*)d_in[3];
    const float* emb_b = (const float*)d_in[4];
    const float* eW1   = (const float*)d_in[5];
    const float* eb1   = (const float*)d_in[6];
    const float* eW2   = (const float*)d_in[7];
    const float* eb2   = (const float*)d_in[8];
    const float* nW1   = (const float*)d_in[9];
    const float* nb1   = (const float*)d_in[10];
    const float* nW2   = (const float*)d_in[11];
    const float* nb2   = (const float*)d_in[12];
    const float* cW1   = (const float*)d_in[13];
    const float* cb1   = (const float*)d_in[14];
    const float* cW2   = (const float*)d_in[15];
    const float* cb2   = (const float*)d_in[16];
    float* out = (float*)d_out;

    cudaFuncSetAttribute(edge_kernel, cudaFuncAttributeMaxDynamicSharedMemorySize, EDGE_SMEM_BYTES);
    cudaFuncSetAttribute(node_kernel, cudaFuncAttributeMaxDynamicSharedMemorySize, NODE_SMEM_BYTES);
    cudaFuncSetAttribute(proj_kernel, cudaFuncAttributeMaxDynamicSharedMemorySize, PROJ_SMEM_BYTES);

    xcopy_kernel<<<(NN * 3 + 255) / 256, 256>>>(x_in);
    embed_kernel<<<(NN * HH + 255) / 256, 256>>>(h_in, emb_W, emb_b);
    prep_kernel<<<(7 * 8192 + 255) / 256, 256>>>(eW1, eW2, cW1, nW1, nW2);
    compose_kernel<<<(8192 + NN + 255) / 256, 256>>>(eW2, cW1, eb2, cb1);
    deg_kernel<<<(EE + 255) / 256, 256>>>(ei);

    const int PB = (NN + TN - 1) / TN;
    for (int l = 0; l < 2; l++) {
        zero_kernel<<<(NN * HH / 4 + 255) / 256, 256>>>();
        proj_kernel<<<PB, NT, PROJ_SMEM_BYTES>>>();
        edge_kernel<<<EE / (TE * TPB), NT, EDGE_SMEM_BYTES>>>(ei, eb1, cW2, cb2, eW1);
        bool fin = (l == 1);
        node_kernel<<<PB, NT, NODE_SMEM_BYTES>>>(
            nb1, nb2, eb2,
            fin ? out : (float*)nullptr,
            fin ? out + (size_t)NN * HH : (float*)nullptr);
    }
}

// round 16
// speedup vs baseline: 1.1962x; 1.1962x over previous
#include <cuda_runtime.h>
#include <cuda_fp16.h>
#include <cstdint>

#define NN 20000
#define EE 640000
#define HH 128
#define TE 128          // edges per tile
#define TPB 4           // tiles per edge block
#define NT 256
#define TN 64           // nodes per block (node/proj kernels)

// Scratch state (device globals: no allocation allowed)
__device__ float g_h[NN * HH];
__device__ float g_x[NN * 3];
__device__ float g_m[NN * HH];      // per-layer: Σ_edges C1 (then @eW2 in node)
__device__ float g_xacc[NN * 3];
__device__ float g_p1[NN * HH];     // h @ eW1[0:128]
__device__ float g_p2[NN * HH];     // h @ eW1[128:256]
__device__ float g_deg[NN];         // edge out-degree
__device__ float g_vb[128];         // eb2 @ cW1 + cb1
// fp16-packed transposed weights, chunk-major [4][128n][16kpair] uint32 each:
// 0=eW1a 1=eW1b 2=eW2 3=cW1(unused) 4=nW1a 5=nW1b 6=nW2 7=Mc(eW2@cW1)
__device__ uint32_t g_wp[8 * 8192];

// ===========================================================================
// helpers
// ===========================================================================
__device__ __forceinline__ uint32_t pack_h2(float a, float b) {
    __half2 h = __floats2half2_rn(a, b);
    return *(uint32_t*)&h;
}

__device__ __forceinline__ void mma16h(float* c,
                                       uint32_t a0, uint32_t a1, uint32_t a2, uint32_t a3,
                                       uint32_t b0, uint32_t b1) {
    asm volatile(
        "mma.sync.aligned.m16n8k16.row.col.f32.f16.f16.f32 "
        "{%0,%1,%2,%3}, {%4,%5,%6,%7}, {%8,%9}, {%0,%1,%2,%3};"
        : "+f"(c[0]), "+f"(c[1]), "+f"(c[2]), "+f"(c[3])
        : "r"(a0), "r"(a1), "r"(a2), "r"(a3), "r"(b0), "r"(b1));
}

__device__ __forceinline__ void red_v4(float* p, float a, float b, float c, float d) {
    asm volatile("red.global.add.v4.f32 [%0], {%1,%2,%3,%4};"
                 :: "l"(p), "f"(a), "f"(b), "f"(c), "f"(d) : "memory");
}

// ===========================================================================
// smem layouts (uint32 indices)
// ===========================================================================
#define PAH 68
// W buffer: full 128x128 fp16 tile = 8192 u32, XOR-swizzled:
//   u32 index of (chunk, n, kp) = chunk*2048 + n*16 + (kp ^ (((n>>1)&3)<<2))
// edge kernel (TE=128)
#define S_ACOL 0                          // 8704 (C1)
#define S_WBUF (S_ACOL + TE * PAH)        // 8192 (Mc, staged once per block)
#define S_EB1  (S_WBUF + 8192)            // 128 (floats)
#define S_W1L  (S_EB1 + 128)
#define S_VB   (S_W1L + 128)
#define S_CW2  (S_VB + 128)
#define S_SROW (S_CW2 + 128)              // int[128]
#define S_SCOL (S_SROW + TE)
#define S_SREL (S_SCOL + TE)              // 128*3 floats
#define S_SRD  (S_SREL + TE * 3)          // 128
#define S_PART (S_SRD + TE)               // 128*2
#define S_TOT  (S_PART + TE * 2)
#define EDGE_SMEM_BYTES (S_TOT * 4)
// node / proj kernels (TN=64)
#define N_AH   0
#define N_AM   (N_AH + TN * PAH)
#define N_WBUF (N_AM + TN * PAH)
#define N_B1   (N_WBUF + 8192)
#define N_B2   (N_B1 + 128)
#define N_EB2  (N_B2 + 128)
#define N_TOT  (N_EB2 + 128)
#define NODE_SMEM_BYTES (N_TOT * 4)
#define P_AH   0
#define P_WBUF (P_AH + TN * PAH)
#define PROJ_SMEM_BYTES ((P_WBUF + 8192) * 4)

// stage full 128x128 W tile into swizzled smem (2048 uint4s, 8/thread)
__device__ __forceinline__ void stage_w(const uint32_t* __restrict__ Wg,
                                        uint32_t* __restrict__ Wbuf, int tid)
{
    __syncthreads();
#pragma unroll
    for (int i = 0; i < 8; i++) {
        int j = tid + 256 * i;
        int chunk = j >> 9;
        int n = (j >> 2) & 127;
        int kq = j & 3;
        *(uint4*)&Wbuf[chunk * 2048 + n * 16 + 4 * (kq ^ ((n >> 1) & 3))] =
            ((const uint4*)Wg)[j];
    }
    __syncthreads();
}

// MMA-only edge pass (W already resident): acc[2][8][4] += As @ W (32x64 warp)
__device__ __forceinline__ void gemm_mma_e(const uint32_t* __restrict__ As,
                                           const uint32_t* __restrict__ Wbuf,
                                           float acc[2][8][4],
                                           int lane, int m_base, int n_base)
{
    const int g = lane >> 2, t = lane & 3;
    const int s = ((g >> 1) & 3) << 2;

#pragma unroll
    for (int ch = 0; ch < 4; ch++) {
        const uint32_t* Wc = Wbuf + ch * 2048;
#pragma unroll
        for (int ks = 0; ks < 2; ks++) {
            const int kp = ch * 16 + ks * 8;
            const uint32_t* A0 = As + (m_base + g) * PAH + kp + t;
            uint32_t a00 = A0[0], a01 = A0[8 * PAH], a02 = A0[4], a03 = A0[8 * PAH + 4];
            const uint32_t* A1 = A0 + 16 * PAH;
            uint32_t a10 = A1[0], a11 = A1[8 * PAH], a12 = A1[4], a13 = A1[8 * PAH + 4];
            const int kb = ks * 8;
#pragma unroll
            for (int nt = 0; nt < 8; nt++) {
                const uint32_t* Bb = Wc + (n_base + nt * 8 + g) * 16;
                uint32_t b0 = Bb[(kb + t) ^ s];
                uint32_t b1 = Bb[(kb + t + 4) ^ s];
                mma16h(acc[0][nt], a00, a01, a02, a03, b0, b1);
                mma16h(acc[1][nt], a10, a11, a12, a13, b0, b1);
            }
        }
    }
}

__device__ __forceinline__ void zacc_e(float acc[2][8][4]) {
#pragma unroll
    for (int m = 0; m < 2; m++)
#pragma unroll
        for (int n = 0; n < 8; n++)
#pragma unroll
            for (int j = 0; j < 4; j++) acc[m][n][j] = 0.0f;
}

// node-side pass (warp tile 32x32, stages W per call)
__device__ __forceinline__ void gemm_pass_h(const uint32_t* __restrict__ As,
                                            const uint32_t* __restrict__ Wg,
                                            uint32_t* __restrict__ Wbuf,
                                            float acc[2][4][4],
                                            int tid, int lane, int m_base, int n_base)
{
    const int g = lane >> 2, t = lane & 3;
    const int s = ((g >> 1) & 3) << 2;

    stage_w(Wg, Wbuf, tid);

#pragma unroll
    for (int ch = 0; ch < 4; ch++) {
        const uint32_t* Wc = Wbuf + ch * 2048;
#pragma unroll
        for (int ks = 0; ks < 2; ks++) {
            const int kp = ch * 16 + ks * 8;
            const uint32_t* A0 = As + (m_base + g) * PAH + kp + t;
            uint32_t a00 = A0[0], a01 = A0[8 * PAH], a02 = A0[4], a03 = A0[8 * PAH + 4];
            const uint32_t* A1 = A0 + 16 * PAH;
            uint32_t a10 = A1[0], a11 = A1[8 * PAH], a12 = A1[4], a13 = A1[8 * PAH + 4];
            const int kb = ks * 8;
#pragma unroll
            for (int nt = 0; nt < 4; nt++) {
                const uint32_t* Bb = Wc + (n_base + nt * 8 + g) * 16;
                uint32_t b0 = Bb[(kb + t) ^ s];
                uint32_t b1 = Bb[(kb + t + 4) ^ s];
                mma16h(acc[0][nt], a00, a01, a02, a03, b0, b1);
                mma16h(acc[1][nt], a10, a11, a12, a13, b0, b1);
            }
        }
    }
}

__device__ __forceinline__ void zacc(float acc[2][4][4]) {
#pragma unroll
    for (int m = 0; m < 2; m++)
#pragma unroll
        for (int n = 0; n < 4; n++)
#pragma unroll
            for (int j = 0; j < 4; j++) acc[m][n][j] = 0.0f;
}

// prep: fp16-pack weight tiles, transposed [n][k], chunk-major
__global__ void prep_kernel(const float* __restrict__ eW1,
                            const float* __restrict__ eW2,
                            const float* __restrict__ cW1,
                            const float* __restrict__ nW1,
                            const float* __restrict__ nW2)
{
    int idx = blockIdx.x * blockDim.x + threadIdx.x;
    if (idx >= 7 * 8192) return;
    int mat = idx >> 13;
    int rem = idx & 8191;
    int chunk = rem >> 11;
    int n = (rem >> 4) & 127;
    int kp = rem & 15;
    int k = chunk * 32 + kp * 2;
    const float* W;
    int off = 0;
    switch (mat) {
        case 0: W = eW1; break;
        case 1: W = eW1; off = 128 * 128; break;
        case 2: W = eW2; break;
        case 3: W = cW1; break;
        case 4: W = nW1; break;
        case 5: W = nW1; off = 128 * 128; break;
        default: W = nW2; break;
    }
    g_wp[idx] = pack_h2(W[off + k * 128 + n], W[off + (k + 1) * 128 + n]);
}

// compose v2: 4 lanes per output + shfl reduce (breaks the 128-FMA chains)
__global__ void compose_kernel(const float* __restrict__ eW2,
                               const float* __restrict__ cW1,
                               const float* __restrict__ eb2,
                               const float* __restrict__ cb1)
{
    int idx = blockIdx.x * blockDim.x + threadIdx.x;
    if (idx < 32768) {
        int q = idx & 3;
        int o = idx >> 2;                  // 0..8191
        int n = o & 127;
        int kp = (o >> 7) & 15;
        int chunk = o >> 11;
        int k = chunk * 32 + kp * 2;
        float s0 = 0.0f, s1 = 0.0f;
        for (int j = q * 32; j < q * 32 + 32; j++) {
            float c = cW1[j * 128 + n];
            s0 = fmaf(eW2[k * 128 + j], c, s0);
            s1 = fmaf(eW2[(k + 1) * 128 + j], c, s1);
        }
        s0 += __shfl_xor_sync(0xffffffffu, s0, 1);
        s0 += __shfl_xor_sync(0xffffffffu, s0, 2);
        s1 += __shfl_xor_sync(0xffffffffu, s1, 1);
        s1 += __shfl_xor_sync(0xffffffffu, s1, 2);
        if (q == 0)
            g_wp[7 * 8192 + chunk * 2048 + n * 16 + kp] = pack_h2(s0, s1);
    } else if (idx < 32768 + 512) {
        int i2 = idx - 32768;
        int q = i2 & 3, n = i2 >> 2;
        float s = (q == 0) ? cb1[n] : 0.0f;
        for (int j = q * 32; j < q * 32 + 32; j++)
            s = fmaf(eb2[j], cW1[j * 128 + n], s);
        s += __shfl_xor_sync(0xffffffffu, s, 1);
        s += __shfl_xor_sync(0xffffffffu, s, 2);
        if (q == 0) g_vb[n] = s;
    } else if (idx - 32768 - 512 < NN) {
        g_deg[idx - 32768 - 512] = 0.0f;
    }
}

__global__ void deg_kernel(const int* __restrict__ ei) {
    int e = blockIdx.x * blockDim.x + threadIdx.x;
    if (e < EE) {
        int r = ei[e];
        if ((unsigned)r >= NN) r = 0;
        atomicAdd(&g_deg[r], 1.0f);
    }
}

// proj: P1 = h @ eW1a, P2 = h @ eW1b  (fp32 out)
__global__ void __launch_bounds__(NT, 3) proj_kernel()
{
    extern __shared__ uint32_t smu[];
    uint32_t* AH   = smu + P_AH;
    uint32_t* Wbuf = smu + P_WBUF;

    const int tid  = threadIdx.x;
    const int lane = tid & 31;
    const int wid  = tid >> 5;
    const int m_base = (wid & 1) * 32;
    const int n_base = (wid >> 1) * 32;
    const int g = lane >> 2, t = lane & 3;
    const int n0 = blockIdx.x * TN;

    for (int j = tid; j < TN * 32; j += NT) {
        int e = j >> 5, c4 = j & 31;
        int n = n0 + e; if (n >= NN) n = NN - 1;
        float4 hv = ((const float4*)(g_h + (size_t)n * HH))[c4];
        *(uint2*)&AH[e * PAH + c4 * 2] =
            make_uint2(pack_h2(hv.x, hv.y), pack_h2(hv.z, hv.w));
    }

    float acc[2][4][4];

#pragma unroll
    for (int pp = 0; pp < 2; pp++) {
        float* dst = pp ? g_p2 : g_p1;
        zacc(acc);
        gemm_pass_h(AH, g_wp + pp * 8192, Wbuf, acc, tid, lane, m_base, n_base);
#pragma unroll
        for (int m = 0; m < 2; m++)
#pragma unroll
            for (int half = 0; half < 2; half++) {
                const int r = m_base + m * 16 + g + half * 8;
                const int n = n0 + r;
                if (n < NN) {
#pragma unroll
                    for (int nt = 0; nt < 4; nt++) {
                        int c = n_base + nt * 8 + t * 2;
                        dst[(size_t)n * HH + c]     = acc[m][nt][half * 2 + 0];
                        dst[(size_t)n * HH + c + 1] = acc[m][nt][half * 2 + 1];
                    }
                }
            }
    }
}

// ---------------------------------------------------------------------------
// Fused edge pass. 4 tiles/block, Mc staged once, 2 CTAs/SM (no reg spill).
//   C1 = relu(P1[row]+P2[col]+rd*w1l+eb1)  -> red.v4 into g_m + fp16 smem
//   alpha = relu(C1 @ Mc + vb) . cW2 + cb2 -> scatter alpha*rel into g_xacc
// ---------------------------------------------------------------------------
__global__ void __launch_bounds__(NT, 2) edge_kernel(
    const int* __restrict__ ei,
    const float* __restrict__ eb1, const float* __restrict__ cW2,
    const float* __restrict__ cb2, const float* __restrict__ eW1)
{
    extern __shared__ uint32_t smu[];
    float* smf = (float*)smu;
    uint32_t* Acol = smu + S_ACOL;      // C1
    uint32_t* Wbuf = smu + S_WBUF;      // Mc, resident for whole block
    int*   srow = (int*)(smu + S_SROW);
    int*   scol = (int*)(smu + S_SCOL);
    float* srel = smf + S_SREL;
    float* srd  = smf + S_SRD;
    float* spart= smf + S_PART;

    const int tid  = threadIdx.x;
    const int lane = tid & 31;
    const int wid  = tid >> 5;
    const int m_base = (wid & 3) * 32;
    const int n_base = (wid >> 2) * 64;
    const int wn = wid >> 2;
    const int g = lane >> 2, t = lane & 3;

    // stage Mc once per block
#pragma unroll
    for (int i = 0; i < 8; i++) {
        int j = tid + 256 * i;
        int chunk = j >> 9;
        int n = (j >> 2) & 127;
        int kq = j & 3;
        *(uint4*)&Wbuf[chunk * 2048 + n * 16 + 4 * (kq ^ ((n >> 1) & 3))] =
            ((const uint4*)(g_wp + 7 * 8192))[j];
    }
    if (tid < 128) {
        smf[S_EB1 + tid] = eb1[tid];
        smf[S_VB  + tid] = g_vb[tid];
        smf[S_CW2 + tid] = cW2[tid];
        smf[S_W1L + tid] = eW1[256 * 128 + tid];
    }
    const float cb2v = cb2[0];

    for (int it = 0; it < TPB; it++) {
        const int e0 = (blockIdx.x * TPB + it) * TE;
        __syncthreads();                // staging (it=0) / prev alpha scatter done

        if (tid < TE) {
            int e = e0 + tid;
            int r = ei[e];
            int c = ei[EE + e];
            if ((unsigned)r >= NN) r = 0;
            if ((unsigned)c >= NN) c = 0;
            srow[tid] = r;
            scol[tid] = c;
            float dx = g_x[r * 3 + 0] - g_x[c * 3 + 0];
            float dy = g_x[r * 3 + 1] - g_x[c * 3 + 1];
            float dz = g_x[r * 3 + 2] - g_x[c * 3 + 2];
            srel[tid * 3 + 0] = dx; srel[tid * 3 + 1] = dy; srel[tid * 3 + 2] = dz;
            srd[tid] = dx * dx + dy * dy + dz * dz;
        }
        __syncthreads();                // indices + srd ready

        // fused gather + C1 epilogue + C1 scatter (m-path)
        for (int j = tid; j < TE * 32; j += NT) {
            int e = j >> 5, c4 = j & 31;
            int c = c4 * 4;
            float4 p1 = ((const float4*)(g_p1 + (size_t)srow[e] * HH))[c4];
            float4 p2 = ((const float4*)(g_p2 + (size_t)scol[e] * HH))[c4];
            float rd = srd[e];
            float v0 = fmaxf(p1.x + p2.x + rd * smf[S_W1L + c]     + smf[S_EB1 + c],     0.0f);
            float v1 = fmaxf(p1.y + p2.y + rd * smf[S_W1L + c + 1] + smf[S_EB1 + c + 1], 0.0f);
            float v2 = fmaxf(p1.z + p2.z + rd * smf[S_W1L + c + 2] + smf[S_EB1 + c + 2], 0.0f);
            float v3 = fmaxf(p1.w + p2.w + rd * smf[S_W1L + c + 3] + smf[S_EB1 + c + 3], 0.0f);
            red_v4(&g_m[(size_t)srow[e] * HH + c], v0, v1, v2, v3);
            *(uint2*)&Acol[e * PAH + c4 * 2] = make_uint2(pack_h2(v0, v1), pack_h2(v2, v3));
        }
        __syncthreads();                // C1 tile ready

        float acc[2][8][4];
        zacc_e(acc);
        gemm_mma_e(Acol, Wbuf, acc, lane, m_base, n_base);

        // alpha epilogue: C3 = relu(acc + vb); alpha = C3 . cW2 + cb2
#pragma unroll
        for (int m = 0; m < 2; m++) {
            const int r0 = m_base + m * 16 + g;
            float p0 = 0.0f, p1 = 0.0f;
#pragma unroll
            for (int nt = 0; nt < 8; nt++) {
                int c = n_base + nt * 8 + t * 2;
                float bA = smf[S_VB + c], bB = smf[S_VB + c + 1];
                float wA = smf[S_CW2 + c], wB = smf[S_CW2 + c + 1];
                p0 = fmaf(fmaxf(acc[m][nt][0] + bA, 0.0f), wA, p0);
                p0 = fmaf(fmaxf(acc[m][nt][1] + bB, 0.0f), wB, p0);
                p1 = fmaf(fmaxf(acc[m][nt][2] + bA, 0.0f), wA, p1);
                p1 = fmaf(fmaxf(acc[m][nt][3] + bB, 0.0f), wB, p1);
            }
            p0 += __shfl_xor_sync(0xffffffffu, p0, 1);
            p0 += __shfl_xor_sync(0xffffffffu, p0, 2);
            p1 += __shfl_xor_sync(0xffffffffu, p1, 1);
            p1 += __shfl_xor_sync(0xffffffffu, p1, 2);
            if (t == 0) {
                spart[r0 * 2 + wn]       = p0;
                spart[(r0 + 8) * 2 + wn] = p1;
            }
        }
        __syncthreads();

        if (tid < TE) {
            float alpha = spart[tid * 2] + spart[tid * 2 + 1] + cb2v;
            int node = srow[tid];
            atomicAdd(&g_xacc[node * 3 + 0], alpha * srel[tid * 3 + 0]);
            atomicAdd(&g_xacc[node * 3 + 1], alpha * srel[tid * 3 + 1]);
            atomicAdd(&g_xacc[node * 3 + 2], alpha * srel[tid * 3 + 2]);
        }
    }
}

// ---------------------------------------------------------------------------
// Node update: m = mc@eW2 + deg*eb2;
//              h += relu([h,m]@nW1+nb1)@nW2+nb2; x += xacc
// ---------------------------------------------------------------------------
__global__ void __launch_bounds__(NT, 3) node_kernel(
    const float* __restrict__ nb1, const float* __restrict__ nb2,
    const float* __restrict__ eb2,
    float* __restrict__ out_h, float* __restrict__ out_x)
{
    extern __shared__ uint32_t smu[];
    float* smf = (float*)smu;
    uint32_t* AH   = smu + N_AH;        // h fp16; reused as C1
    uint32_t* AM   = smu + N_AM;        // mc fp16 -> m fp16
    uint32_t* Wbuf = smu + N_WBUF;

    const int tid  = threadIdx.x;
    const int lane = tid & 31;
    const int wid  = tid >> 5;
    const int m_base = (wid & 1) * 32;
    const int n_base = (wid >> 1) * 32;
    const int g = lane >> 2, t = lane & 3;
    const int n0 = blockIdx.x * TN;

    if (tid < 128) {
        smf[N_B1 + tid] = nb1[tid];
        smf[N_B2 + tid] = nb2[tid];
        smf[N_EB2 + tid] = eb2[tid];
    }

    for (int j = tid; j < TN * 32; j += NT) {
        int e = j >> 5, c4 = j & 31;
        int n = n0 + e; if (n >= NN) n = NN - 1;
        float4 hv = ((const float4*)(g_h + (size_t)n * HH))[c4];
        float4 mv = ((const float4*)(g_m + (size_t)n * HH))[c4];
        *(uint2*)&AH[e * PAH + c4 * 2] =
            make_uint2(pack_h2(hv.x, hv.y), pack_h2(hv.z, hv.w));
        *(uint2*)&AM[e * PAH + c4 * 2] =
            make_uint2(pack_h2(mv.x, mv.y), pack_h2(mv.z, mv.w));
    }

    float acc[2][4][4];

    // ---- m-GEMM: m = mc @ eW2 + deg*eb2 ----
    zacc(acc);
    gemm_pass_h(AM, g_wp + 2 * 8192, Wbuf, acc, tid, lane, m_base, n_base);
    __syncthreads();        // all warps done reading AM before overwrite
#pragma unroll
    for (int m = 0; m < 2; m++) {
        const int r0 = m_base + m * 16 + g, r1 = r0 + 8;
        int na = n0 + r0, nb = n0 + r1;
        float da = (na < NN) ? g_deg[na] : 0.0f;
        float db = (nb < NN) ? g_deg[nb] : 0.0f;
#pragma unroll
        for (int nt = 0; nt < 4; nt++) {
            int c = n_base + nt * 8 + t * 2;
            float eA = smf[N_EB2 + c], eB = smf[N_EB2 + c + 1];
            AM[r0 * PAH + (c >> 1)] = pack_h2(acc[m][nt][0] + da * eA,
                                              acc[m][nt][1] + da * eB);
            AM[r1 * PAH + (c >> 1)] = pack_h2(acc[m][nt][2] + db * eA,
                                              acc[m][nt][3] + db * eB);
        }
    }

    // GEMM1: [h|m] @ nW1  (stage_w's leading sync orders AM writes)
    zacc(acc);
    gemm_pass_h(AH, g_wp + 4 * 8192, Wbuf, acc, tid, lane, m_base, n_base);
    gemm_pass_h(AM, g_wp + 5 * 8192, Wbuf, acc, tid, lane, m_base, n_base);
    __syncthreads();        // all warps done reading AH before C1 overwrite

    // epilogue 1: relu(+nb1) -> fp16 into AH (reused as C1)
#pragma unroll
    for (int m = 0; m < 2; m++) {
        const int r0 = m_base + m * 16 + g, r1 = r0 + 8;
#pragma unroll
        for (int nt = 0; nt < 4; nt++) {
            int c = n_base + nt * 8 + t * 2;
            float bA = smf[N_B1 + c], bB = smf[N_B1 + c + 1];
            AH[r0 * PAH + (c >> 1)] = pack_h2(fmaxf(acc[m][nt][0] + bA, 0.0f),
                                              fmaxf(acc[m][nt][1] + bB, 0.0f));
            AH[r1 * PAH + (c >> 1)] = pack_h2(fmaxf(acc[m][nt][2] + bA, 0.0f),
                                              fmaxf(acc[m][nt][3] + bB, 0.0f));
        }
    }

    // GEMM2: C1 @ nW2
    zacc(acc);
    gemm_pass_h(AH, g_wp + 6 * 8192, Wbuf, acc, tid, lane, m_base, n_base);

    // epilogue 2: h_new = h_old + acc + nb2 -> g_h (+ out)
#pragma unroll
    for (int m = 0; m < 2; m++) {
#pragma unroll
        for (int half = 0; half < 2; half++) {
            const int r = m_base + m * 16 + g + half * 8;
            const int n = n0 + r;
            if (n < NN) {
#pragma unroll
                for (int nt = 0; nt < 4; nt++) {
                    int c = n_base + nt * 8 + t * 2;
                    float a0 = acc[m][nt][half * 2 + 0];
                    float a1 = acc[m][nt][half * 2 + 1];
                    float h0 = g_h[(size_t)n * HH + c]     + a0 + smf[N_B2 + c];
                    float h1 = g_h[(size_t)n * HH + c + 1] + a1 + smf[N_B2 + c + 1];
                    g_h[(size_t)n * HH + c]     = h0;
                    g_h[(size_t)n * HH + c + 1] = h1;
                    if (out_h) {
                        out_h[(size_t)n * HH + c]     = h0;
                        out_h[(size_t)n * HH + c + 1] = h1;
                    }
                }
            }
        }
    }

    for (int tt = tid; tt < TN * 3; tt += NT) {
        int n = n0 + tt / 3;
        if (n < NN) {
            int d = tt % 3;
            float xv = g_x[n * 3 + d] + g_xacc[n * 3 + d];
            g_x[n * 3 + d] = xv;
            if (out_x) out_x[n * 3 + d] = xv;
        }
    }
}

// ===========================================================================
// small setup kernels
// ===========================================================================
__global__ void embed_kernel(const float* __restrict__ hin,
                             const float* __restrict__ W,
                             const float* __restrict__ b)
{
    int j = blockIdx.x * blockDim.x + threadIdx.x;
    if (j >= NN * HH) return;
    int n = j >> 7, c = j & 127;
    float acc = b[c];
#pragma unroll
    for (int k = 0; k < 16; k++)
        acc = fmaf(hin[n * 16 + k], W[k * 128 + c], acc);
    g_h[j] = acc;
}

__global__ void xcopy_kernel(const float* __restrict__ xin)
{
    int i = blockIdx.x * blockDim.x + threadIdx.x;
    if (i < NN * 3) g_x[i] = xin[i];
}

__global__ void zero_kernel()
{
    int i = blockIdx.x * blockDim.x + threadIdx.x;
    if (i < NN * HH / 4) ((float4*)g_m)[i] = make_float4(0.f, 0.f, 0.f, 0.f);
    if (i < NN * 3 / 4) ((float4*)g_xacc)[i] = make_float4(0.f, 0.f, 0.f, 0.f);
}

extern "C" void kernel_launch(void* const* d_in, const int* in_sizes, int n_in,
                              void* d_out, int out_size)
{
    const float* h_in  = (const float*)d_in[0];
    const float* x_in  = (const float*)d_in[1];
    const int*   ei    = (const int*)d_in[2];
    const float* emb_W = (const float*)d_in[3];
    const float* emb_b = (const float*)d_in[4];
    const float* eW1   = (const float*)d_in[5];
    const float* eb1   = (const float*)d_in[6];
    const float* eW2   = (const float*)d_in[7];
    const float* eb2   = (const float*)d_in[8];
    const float* nW1   = (const float*)d_in[9];
    const float* nb1   = (const float*)d_in[10];
    const float* nW2   = (const float*)d_in[11];
    const float* nb2   = (const float*)d_in[12];
    const float* cW1   = (const float*)d_in[13];
    const float* cb1   = (const float*)d_in[14];
    const float* cW2   = (const float*)d_in[15];
    const float* cb2   = (const float*)d_in[16];
    float* out = (float*)d_out;

    cudaFuncSetAttribute(edge_kernel, cudaFuncAttributeMaxDynamicSharedMemorySize, EDGE_SMEM_BYTES);
    cudaFuncSetAttribute(node_kernel, cudaFuncAttributeMaxDynamicSharedMemorySize, NODE_SMEM_BYTES);
    cudaFuncSetAttribute(proj_kernel, cudaFuncAttributeMaxDynamicSharedMemorySize, PROJ_SMEM_BYTES);

    xcopy_kernel<<<(NN * 3 + 255) / 256, 256>>>(x_in);
    embed_kernel<<<(NN * HH + 255) / 256, 256>>>(h_in, emb_W, emb_b);
    prep_kernel<<<(7 * 8192 + 255) / 256, 256>>>(eW1, eW2, cW1, nW1, nW2);
    compose_kernel<<<(32768 + 512 + NN + 255) / 256, 256>>>(eW2, cW1, eb2, cb1);
    deg_kernel<<<(EE + 255) / 256, 256>>>(ei);

    const int PB = (NN + TN - 1) / TN;
    for (int l = 0; l < 2; l++) {
        zero_kernel<<<(NN * HH / 4 + 255) / 256, 256>>>();
        proj_kernel<<<PB, NT, PROJ_SMEM_BYTES>>>();
        edge_kernel<<<EE / (TE * TPB), NT, EDGE_SMEM_BYTES>>>(ei, eb1, cW2, cb2, eW1);
        bool fin = (l == 1);
        node_kernel<<<PB, NT, NODE_SMEM_BYTES>>>(
            nb1, nb2, eb2,
            fin ? out : (float*)nullptr,
            fin ? out + (size_t)NN * HH : (float*)nullptr);
    }
}

// round 17
// speedup vs baseline: 1.3192x; 1.1029x over previous
#include <cuda_runtime.h>
#include <cuda_fp16.h>
#include <cstdint>

#define NN 20000
#define EE 640000
#define HH 128
#define TE 128          // edges per block (edge kernel)
#define NT 256
#define TN 64           // nodes per block (node/proj kernels)

// Scratch state (device globals: no allocation allowed)
__device__ float g_h[NN * HH];
__device__ float g_x[NN * 3];
__device__ float g_m[NN * HH];      // per-layer: Σ_edges C1 (then @eW2 in node)
__device__ float g_xacc[NN * 3];
__device__ float g_p1[NN * HH];     // h @ eW1[0:128]
__device__ float g_p2[NN * HH];     // h @ eW1[128:256]
__device__ float g_deg[NN];         // edge out-degree
__device__ float g_vb[128];         // eb2 @ cW1 + cb1
// fp16-packed transposed weights, chunk-major [4][128n][16kpair] uint32 each:
// 0=eW1a 1=eW1b 2=eW2 3=cW1(unused) 4=nW1a 5=nW1b 6=nW2 7=Mc(eW2@cW1)
__device__ uint32_t g_wp[8 * 8192];

// ===========================================================================
// helpers
// ===========================================================================
__device__ __forceinline__ uint32_t pack_h2(float a, float b) {
    __half2 h = __floats2half2_rn(a, b);
    return *(uint32_t*)&h;
}

__device__ __forceinline__ void mma16h(float* c,
                                       uint32_t a0, uint32_t a1, uint32_t a2, uint32_t a3,
                                       uint32_t b0, uint32_t b1) {
    asm volatile(
        "mma.sync.aligned.m16n8k16.row.col.f32.f16.f16.f32 "
        "{%0,%1,%2,%3}, {%4,%5,%6,%7}, {%8,%9}, {%0,%1,%2,%3};"
        : "+f"(c[0]), "+f"(c[1]), "+f"(c[2]), "+f"(c[3])
        : "r"(a0), "r"(a1), "r"(a2), "r"(a3), "r"(b0), "r"(b1));
}

__device__ __forceinline__ void red_v4(float* p, float a, float b, float c, float d) {
    asm volatile("red.global.add.v4.f32 [%0], {%1,%2,%3,%4};"
                 :: "l"(p), "f"(a), "f"(b), "f"(c), "f"(d) : "memory");
}

// ===========================================================================
// smem layouts (uint32 indices)
// ===========================================================================
#define PAH 68
// W buffer: full 128x128 fp16 tile = 8192 u32, XOR-swizzled:
//   u32 index of (chunk, n, kp) = chunk*2048 + n*16 + (kp ^ (((n>>1)&3)<<2))
// edge kernel (TE=128)
#define S_ACOL 0                          // 8704 (C1)
#define S_WBUF (S_ACOL + TE * PAH)        // 8192 (Mc)
#define S_EB1  (S_WBUF + 8192)            // 128 (floats)
#define S_W1L  (S_EB1 + 128)
#define S_VB   (S_W1L + 128)
#define S_CW2  (S_VB + 128)
#define S_SROW (S_CW2 + 128)              // int[128]
#define S_SCOL (S_SROW + TE)
#define S_SREL (S_SCOL + TE)              // 128*3 floats
#define S_SRD  (S_SREL + TE * 3)          // 128
#define S_PART (S_SRD + TE)               // 128*2
#define S_TOT  (S_PART + TE * 2)
#define EDGE_SMEM_BYTES (S_TOT * 4)
// node / proj kernels (TN=64)
#define N_AH   0
#define N_AM   (N_AH + TN * PAH)
#define N_WBUF (N_AM + TN * PAH)
#define N_B1   (N_WBUF + 8192)
#define N_B2   (N_B1 + 128)
#define N_EB2  (N_B2 + 128)
#define N_TOT  (N_EB2 + 128)
#define NODE_SMEM_BYTES (N_TOT * 4)
#define P_AH   0
#define P_WBUF (P_AH + TN * PAH)
#define PROJ_SMEM_BYTES ((P_WBUF + 8192) * 4)

// stage full 128x128 W tile into swizzled smem (2048 uint4s, 8/thread)
__device__ __forceinline__ void stage_w(const uint32_t* __restrict__ Wg,
                                        uint32_t* __restrict__ Wbuf, int tid)
{
    __syncthreads();
#pragma unroll
    for (int i = 0; i < 8; i++) {
        int j = tid + 256 * i;
        int chunk = j >> 9;
        int n = (j >> 2) & 127;
        int kq = j & 3;
        *(uint4*)&Wbuf[chunk * 2048 + n * 16 + 4 * (kq ^ ((n >> 1) & 3))] =
            ((const uint4*)Wg)[j];
    }
    __syncthreads();
}

// MMA-only edge pass (W already resident): acc[2][8][4] += As @ W (32x64 warp)
__device__ __forceinline__ void gemm_mma_e(const uint32_t* __restrict__ As,
                                           const uint32_t* __restrict__ Wbuf,
                                           float acc[2][8][4],
                                           int lane, int m_base, int n_base)
{
    const int g = lane >> 2, t = lane & 3;
    const int s = ((g >> 1) & 3) << 2;

#pragma unroll
    for (int ch = 0; ch < 4; ch++) {
        const uint32_t* Wc = Wbuf + ch * 2048;
#pragma unroll
        for (int ks = 0; ks < 2; ks++) {
            const int kp = ch * 16 + ks * 8;
            const uint32_t* A0 = As + (m_base + g) * PAH + kp + t;
            uint32_t a00 = A0[0], a01 = A0[8 * PAH], a02 = A0[4], a03 = A0[8 * PAH + 4];
            const uint32_t* A1 = A0 + 16 * PAH;
            uint32_t a10 = A1[0], a11 = A1[8 * PAH], a12 = A1[4], a13 = A1[8 * PAH + 4];
            const int kb = ks * 8;
#pragma unroll
            for (int nt = 0; nt < 8; nt++) {
                const uint32_t* Bb = Wc + (n_base + nt * 8 + g) * 16;
                uint32_t b0 = Bb[(kb + t) ^ s];
                uint32_t b1 = Bb[(kb + t + 4) ^ s];
                mma16h(acc[0][nt], a00, a01, a02, a03, b0, b1);
                mma16h(acc[1][nt], a10, a11, a12, a13, b0, b1);
            }
        }
    }
}

__device__ __forceinline__ void zacc_e(float acc[2][8][4]) {
#pragma unroll
    for (int m = 0; m < 2; m++)
#pragma unroll
        for (int n = 0; n < 8; n++)
#pragma unroll
            for (int j = 0; j < 4; j++) acc[m][n][j] = 0.0f;
}

// node-side pass (warp tile 32x32, stages W per call)
__device__ __forceinline__ void gemm_pass_h(const uint32_t* __restrict__ As,
                                            const uint32_t* __restrict__ Wg,
                                            uint32_t* __restrict__ Wbuf,
                                            float acc[2][4][4],
                                            int tid, int lane, int m_base, int n_base)
{
    const int g = lane >> 2, t = lane & 3;
    const int s = ((g >> 1) & 3) << 2;

    stage_w(Wg, Wbuf, tid);

#pragma unroll
    for (int ch = 0; ch < 4; ch++) {
        const uint32_t* Wc = Wbuf + ch * 2048;
#pragma unroll
        for (int ks = 0; ks < 2; ks++) {
            const int kp = ch * 16 + ks * 8;
            const uint32_t* A0 = As + (m_base + g) * PAH + kp + t;
            uint32_t a00 = A0[0], a01 = A0[8 * PAH], a02 = A0[4], a03 = A0[8 * PAH + 4];
            const uint32_t* A1 = A0 + 16 * PAH;
            uint32_t a10 = A1[0], a11 = A1[8 * PAH], a12 = A1[4], a13 = A1[8 * PAH + 4];
            const int kb = ks * 8;
#pragma unroll
            for (int nt = 0; nt < 4; nt++) {
                const uint32_t* Bb = Wc + (n_base + nt * 8 + g) * 16;
                uint32_t b0 = Bb[(kb + t) ^ s];
                uint32_t b1 = Bb[(kb + t + 4) ^ s];
                mma16h(acc[0][nt], a00, a01, a02, a03, b0, b1);
                mma16h(acc[1][nt], a10, a11, a12, a13, b0, b1);
            }
        }
    }
}

__device__ __forceinline__ void zacc(float acc[2][4][4]) {
#pragma unroll
    for (int m = 0; m < 2; m++)
#pragma unroll
        for (int n = 0; n < 4; n++)
#pragma unroll
            for (int j = 0; j < 4; j++) acc[m][n][j] = 0.0f;
}

// prep: fp16-pack weight tiles, transposed [n][k], chunk-major
__global__ void prep_kernel(const float* __restrict__ eW1,
                            const float* __restrict__ eW2,
                            const float* __restrict__ cW1,
                            const float* __restrict__ nW1,
                            const float* __restrict__ nW2)
{
    int idx = blockIdx.x * blockDim.x + threadIdx.x;
    if (idx >= 7 * 8192) return;
    int mat = idx >> 13;
    int rem = idx & 8191;
    int chunk = rem >> 11;
    int n = (rem >> 4) & 127;
    int kp = rem & 15;
    int k = chunk * 32 + kp * 2;
    const float* W;
    int off = 0;
    switch (mat) {
        case 0: W = eW1; break;
        case 1: W = eW1; off = 128 * 128; break;
        case 2: W = eW2; break;
        case 3: W = cW1; break;
        case 4: W = nW1; break;
        case 5: W = nW1; off = 128 * 128; break;
        default: W = nW2; break;
    }
    g_wp[idx] = pack_h2(W[off + k * 128 + n], W[off + (k + 1) * 128 + n]);
}

// compose v2: 4 lanes per output + shfl reduce (breaks the 128-FMA chains)
__global__ void compose_kernel(const float* __restrict__ eW2,
                               const float* __restrict__ cW1,
                               const float* __restrict__ eb2,
                               const float* __restrict__ cb1)
{
    int idx = blockIdx.x * blockDim.x + threadIdx.x;
    if (idx < 32768) {
        int q = idx & 3;
        int o = idx >> 2;                  // 0..8191
        int n = o & 127;
        int kp = (o >> 7) & 15;
        int chunk = o >> 11;
        int k = chunk * 32 + kp * 2;
        float s0 = 0.0f, s1 = 0.0f;
        for (int j = q * 32; j < q * 32 + 32; j++) {
            float c = cW1[j * 128 + n];
            s0 = fmaf(eW2[k * 128 + j], c, s0);
            s1 = fmaf(eW2[(k + 1) * 128 + j], c, s1);
        }
        s0 += __shfl_xor_sync(0xffffffffu, s0, 1);
        s0 += __shfl_xor_sync(0xffffffffu, s0, 2);
        s1 += __shfl_xor_sync(0xffffffffu, s1, 1);
        s1 += __shfl_xor_sync(0xffffffffu, s1, 2);
        if (q == 0)
            g_wp[7 * 8192 + chunk * 2048 + n * 16 + kp] = pack_h2(s0, s1);
    } else if (idx < 32768 + 512) {
        int i2 = idx - 32768;
        int q = i2 & 3, n = i2 >> 2;
        float s = (q == 0) ? cb1[n] : 0.0f;
        for (int j = q * 32; j < q * 32 + 32; j++)
            s = fmaf(eb2[j], cW1[j * 128 + n], s);
        s += __shfl_xor_sync(0xffffffffu, s, 1);
        s += __shfl_xor_sync(0xffffffffu, s, 2);
        if (q == 0) g_vb[n] = s;
    } else if (idx - 32768 - 512 < NN) {
        g_deg[idx - 32768 - 512] = 0.0f;
    }
}

__global__ void deg_kernel(const int* __restrict__ ei) {
    int e = blockIdx.x * blockDim.x + threadIdx.x;
    if (e < EE) {
        int r = ei[e];
        if ((unsigned)r >= NN) r = 0;
        atomicAdd(&g_deg[r], 1.0f);
    }
}

// proj: P1 = h @ eW1a, P2 = h @ eW1b  (fp32 out)
__global__ void __launch_bounds__(NT, 3) proj_kernel()
{
    extern __shared__ uint32_t smu[];
    uint32_t* AH   = smu + P_AH;
    uint32_t* Wbuf = smu + P_WBUF;

    const int tid  = threadIdx.x;
    const int lane = tid & 31;
    const int wid  = tid >> 5;
    const int m_base = (wid & 1) * 32;
    const int n_base = (wid >> 1) * 32;
    const int g = lane >> 2, t = lane & 3;
    const int n0 = blockIdx.x * TN;

    for (int j = tid; j < TN * 32; j += NT) {
        int e = j >> 5, c4 = j & 31;
        int n = n0 + e; if (n >= NN) n = NN - 1;
        float4 hv = ((const float4*)(g_h + (size_t)n * HH))[c4];
        *(uint2*)&AH[e * PAH + c4 * 2] =
            make_uint2(pack_h2(hv.x, hv.y), pack_h2(hv.z, hv.w));
    }

    float acc[2][4][4];

#pragma unroll
    for (int pp = 0; pp < 2; pp++) {
        float* dst = pp ? g_p2 : g_p1;
        zacc(acc);
        gemm_pass_h(AH, g_wp + pp * 8192, Wbuf, acc, tid, lane, m_base, n_base);
#pragma unroll
        for (int m = 0; m < 2; m++)
#pragma unroll
            for (int half = 0; half < 2; half++) {
                const int r = m_base + m * 16 + g + half * 8;
                const int n = n0 + r;
                if (n < NN) {
#pragma unroll
                    for (int nt = 0; nt < 4; nt++) {
                        int c = n_base + nt * 8 + t * 2;
                        dst[(size_t)n * HH + c]     = acc[m][nt][half * 2 + 0];
                        dst[(size_t)n * HH + c + 1] = acc[m][nt][half * 2 + 1];
                    }
                }
            }
    }
}

// ---------------------------------------------------------------------------
// Fused edge pass (R14 structure: 1 tile/block, grid=5000, 2 CTAs/SM).
//   C1 = relu(P1[row]+P2[col]+rd*w1l+eb1)  -> red.v4 into g_m + fp16 smem
//   alpha = relu(C1 @ Mc + vb) . cW2 + cb2 -> scatter alpha*rel into g_xacc
// ---------------------------------------------------------------------------
__global__ void __launch_bounds__(NT, 2) edge_kernel(
    const int* __restrict__ ei,
    const float* __restrict__ eb1, const float* __restrict__ cW2,
    const float* __restrict__ cb2, const float* __restrict__ eW1)
{
    extern __shared__ uint32_t smu[];
    float* smf = (float*)smu;
    uint32_t* Acol = smu + S_ACOL;      // C1
    uint32_t* Wbuf = smu + S_WBUF;      // Mc
    int*   srow = (int*)(smu + S_SROW);
    int*   scol = (int*)(smu + S_SCOL);
    float* srel = smf + S_SREL;
    float* srd  = smf + S_SRD;
    float* spart= smf + S_PART;

    const int tid  = threadIdx.x;
    const int lane = tid & 31;
    const int wid  = tid >> 5;
    const int m_base = (wid & 3) * 32;
    const int n_base = (wid >> 2) * 64;
    const int wn = wid >> 2;
    const int g = lane >> 2, t = lane & 3;
    const int e0 = blockIdx.x * TE;

    // stage Mc (swizzled) while index/scalar loads proceed
#pragma unroll
    for (int i = 0; i < 8; i++) {
        int j = tid + 256 * i;
        int chunk = j >> 9;
        int n = (j >> 2) & 127;
        int kq = j & 3;
        *(uint4*)&Wbuf[chunk * 2048 + n * 16 + 4 * (kq ^ ((n >> 1) & 3))] =
            ((const uint4*)(g_wp + 7 * 8192))[j];
    }
    if (tid < TE) {
        int e = e0 + tid;
        int r = ei[e];
        int c = ei[EE + e];
        if ((unsigned)r >= NN) r = 0;
        if ((unsigned)c >= NN) c = 0;
        srow[tid] = r;
        scol[tid] = c;
        float dx = g_x[r * 3 + 0] - g_x[c * 3 + 0];
        float dy = g_x[r * 3 + 1] - g_x[c * 3 + 1];
        float dz = g_x[r * 3 + 2] - g_x[c * 3 + 2];
        srel[tid * 3 + 0] = dx; srel[tid * 3 + 1] = dy; srel[tid * 3 + 2] = dz;
        srd[tid] = dx * dx + dy * dy + dz * dz;
    }
    if (tid < 128) {
        smf[S_EB1 + tid] = eb1[tid];
        smf[S_VB  + tid] = g_vb[tid];
        smf[S_CW2 + tid] = cW2[tid];
        smf[S_W1L + tid] = eW1[256 * 128 + tid];
    }
    __syncthreads();

    // fused gather + C1 epilogue + C1 scatter (m-path)
    for (int j = tid; j < TE * 32; j += NT) {
        int e = j >> 5, c4 = j & 31;
        int c = c4 * 4;
        float4 p1 = ((const float4*)(g_p1 + (size_t)srow[e] * HH))[c4];
        float4 p2 = ((const float4*)(g_p2 + (size_t)scol[e] * HH))[c4];
        float rd = srd[e];
        float v0 = fmaxf(p1.x + p2.x + rd * smf[S_W1L + c]     + smf[S_EB1 + c],     0.0f);
        float v1 = fmaxf(p1.y + p2.y + rd * smf[S_W1L + c + 1] + smf[S_EB1 + c + 1], 0.0f);
        float v2 = fmaxf(p1.z + p2.z + rd * smf[S_W1L + c + 2] + smf[S_EB1 + c + 2], 0.0f);
        float v3 = fmaxf(p1.w + p2.w + rd * smf[S_W1L + c + 3] + smf[S_EB1 + c + 3], 0.0f);
        red_v4(&g_m[(size_t)srow[e] * HH + c], v0, v1, v2, v3);
        *(uint2*)&Acol[e * PAH + c4 * 2] = make_uint2(pack_h2(v0, v1), pack_h2(v2, v3));
    }
    __syncthreads();                // C1 tile ready

    float acc[2][8][4];
    zacc_e(acc);
    gemm_mma_e(Acol, Wbuf, acc, lane, m_base, n_base);

    // alpha epilogue: C3 = relu(acc + vb); alpha = C3 . cW2 + cb2
#pragma unroll
    for (int m = 0; m < 2; m++) {
        const int r0 = m_base + m * 16 + g;
        float p0 = 0.0f, p1 = 0.0f;
#pragma unroll
        for (int nt = 0; nt < 8; nt++) {
            int c = n_base + nt * 8 + t * 2;
            float bA = smf[S_VB + c], bB = smf[S_VB + c + 1];
            float wA = smf[S_CW2 + c], wB = smf[S_CW2 + c + 1];
            p0 = fmaf(fmaxf(acc[m][nt][0] + bA, 0.0f), wA, p0);
            p0 = fmaf(fmaxf(acc[m][nt][1] + bB, 0.0f), wB, p0);
            p1 = fmaf(fmaxf(acc[m][nt][2] + bA, 0.0f), wA, p1);
            p1 = fmaf(fmaxf(acc[m][nt][3] + bB, 0.0f), wB, p1);
        }
        p0 += __shfl_xor_sync(0xffffffffu, p0, 1);
        p0 += __shfl_xor_sync(0xffffffffu, p0, 2);
        p1 += __shfl_xor_sync(0xffffffffu, p1, 1);
        p1 += __shfl_xor_sync(0xffffffffu, p1, 2);
        if (t == 0) {
            spart[r0 * 2 + wn]       = p0;
            spart[(r0 + 8) * 2 + wn] = p1;
        }
    }
    __syncthreads();

    if (tid < TE) {
        float alpha = spart[tid * 2] + spart[tid * 2 + 1] + cb2[0];
        int node = srow[tid];
        atomicAdd(&g_xacc[node * 3 + 0], alpha * srel[tid * 3 + 0]);
        atomicAdd(&g_xacc[node * 3 + 1], alpha * srel[tid * 3 + 1]);
        atomicAdd(&g_xacc[node * 3 + 2], alpha * srel[tid * 3 + 2]);
    }
}

// ---------------------------------------------------------------------------
// Node update: m = mc@eW2 + deg*eb2;
//              h += relu([h,m]@nW1+nb1)@nW2+nb2; x += xacc
// ---------------------------------------------------------------------------
__global__ void __launch_bounds__(NT, 3) node_kernel(
    const float* __restrict__ nb1, const float* __restrict__ nb2,
    const float* __restrict__ eb2,
    float* __restrict__ out_h, float* __restrict__ out_x)
{
    extern __shared__ uint32_t smu[];
    float* smf = (float*)smu;
    uint32_t* AH   = smu + N_AH;        // h fp16; reused as C1
    uint32_t* AM   = smu + N_AM;        // mc fp16 -> m fp16
    uint32_t* Wbuf = smu + N_WBUF;

    const int tid  = threadIdx.x;
    const int lane = tid & 31;
    const int wid  = tid >> 5;
    const int m_base = (wid & 1) * 32;
    const int n_base = (wid >> 1) * 32;
    const int g = lane >> 2, t = lane & 3;
    const int n0 = blockIdx.x * TN;

    if (tid < 128) {
        smf[N_B1 + tid] = nb1[tid];
        smf[N_B2 + tid] = nb2[tid];
        smf[N_EB2 + tid] = eb2[tid];
    }

    for (int j = tid; j < TN * 32; j += NT) {
        int e = j >> 5, c4 = j & 31;
        int n = n0 + e; if (n >= NN) n = NN - 1;
        float4 hv = ((const float4*)(g_h + (size_t)n * HH))[c4];
        float4 mv = ((const float4*)(g_m + (size_t)n * HH))[c4];
        *(uint2*)&AH[e * PAH + c4 * 2] =
            make_uint2(pack_h2(hv.x, hv.y), pack_h2(hv.z, hv.w));
        *(uint2*)&AM[e * PAH + c4 * 2] =
            make_uint2(pack_h2(mv.x, mv.y), pack_h2(mv.z, mv.w));
    }

    float acc[2][4][4];

    // ---- m-GEMM: m = mc @ eW2 + deg*eb2 ----
    zacc(acc);
    gemm_pass_h(AM, g_wp + 2 * 8192, Wbuf, acc, tid, lane, m_base, n_base);
    __syncthreads();        // all warps done reading AM before overwrite
#pragma unroll
    for (int m = 0; m < 2; m++) {
        const int r0 = m_base + m * 16 + g, r1 = r0 + 8;
        int na = n0 + r0, nb = n0 + r1;
        float da = (na < NN) ? g_deg[na] : 0.0f;
        float db = (nb < NN) ? g_deg[nb] : 0.0f;
#pragma unroll
        for (int nt = 0; nt < 4; nt++) {
            int c = n_base + nt * 8 + t * 2;
            float eA = smf[N_EB2 + c], eB = smf[N_EB2 + c + 1];
            AM[r0 * PAH + (c >> 1)] = pack_h2(acc[m][nt][0] + da * eA,
                                              acc[m][nt][1] + da * eB);
            AM[r1 * PAH + (c >> 1)] = pack_h2(acc[m][nt][2] + db * eA,
                                              acc[m][nt][3] + db * eB);
        }
    }

    // GEMM1: [h|m] @ nW1  (stage_w's leading sync orders AM writes)
    zacc(acc);
    gemm_pass_h(AH, g_wp + 4 * 8192, Wbuf, acc, tid, lane, m_base, n_base);
    gemm_pass_h(AM, g_wp + 5 * 8192, Wbuf, acc, tid, lane, m_base, n_base);
    __syncthreads();        // all warps done reading AH before C1 overwrite

    // epilogue 1: relu(+nb1) -> fp16 into AH (reused as C1)
#pragma unroll
    for (int m = 0; m < 2; m++) {
        const int r0 = m_base + m * 16 + g, r1 = r0 + 8;
#pragma unroll
        for (int nt = 0; nt < 4; nt++) {
            int c = n_base + nt * 8 + t * 2;
            float bA = smf[N_B1 + c], bB = smf[N_B1 + c + 1];
            AH[r0 * PAH + (c >> 1)] = pack_h2(fmaxf(acc[m][nt][0] + bA, 0.0f),
                                              fmaxf(acc[m][nt][1] + bB, 0.0f));
            AH[r1 * PAH + (c >> 1)] = pack_h2(fmaxf(acc[m][nt][2] + bA, 0.0f),
                                              fmaxf(acc[m][nt][3] + bB, 0.0f));
        }
    }

    // GEMM2: C1 @ nW2
    zacc(acc);
    gemm_pass_h(AH, g_wp + 6 * 8192, Wbuf, acc, tid, lane, m_base, n_base);

    // epilogue 2: h_new = h_old + acc + nb2 -> g_h (+ out)
#pragma unroll
    for (int m = 0; m < 2; m++) {
#pragma unroll
        for (int half = 0; half < 2; half++) {
            const int r = m_base + m * 16 + g + half * 8;
            const int n = n0 + r;
            if (n < NN) {
#pragma unroll
                for (int nt = 0; nt < 4; nt++) {
                    int c = n_base + nt * 8 + t * 2;
                    float a0 = acc[m][nt][half * 2 + 0];
                    float a1 = acc[m][nt][half * 2 + 1];
                    float h0 = g_h[(size_t)n * HH + c]     + a0 + smf[N_B2 + c];
                    float h1 = g_h[(size_t)n * HH + c + 1] + a1 + smf[N_B2 + c + 1];
                    g_h[(size_t)n * HH + c]     = h0;
                    g_h[(size_t)n * HH + c + 1] = h1;
                    if (out_h) {
                        out_h[(size_t)n * HH + c]     = h0;
                        out_h[(size_t)n * HH + c + 1] = h1;
                    }
                }
            }
        }
    }

    for (int tt = tid; tt < TN * 3; tt += NT) {
        int n = n0 + tt / 3;
        if (n < NN) {
            int d = tt % 3;
            float xv = g_x[n * 3 + d] + g_xacc[n * 3 + d];
            g_x[n * 3 + d] = xv;
            if (out_x) out_x[n * 3 + d] = xv;
        }
    }
}

// ===========================================================================
// small setup kernels
// ===========================================================================
__global__ void embed_kernel(const float* __restrict__ hin,
                             const float* __restrict__ W,
                             const float* __restrict__ b)
{
    int j = blockIdx.x * blockDim.x + threadIdx.x;
    if (j >= NN * HH) return;
    int n = j >> 7, c = j & 127;
    float acc = b[c];
#pragma unroll
    for (int k = 0; k < 16; k++)
        acc = fmaf(hin[n * 16 + k], W[k * 128 + c], acc);
    g_h[j] = acc;
}

__global__ void xcopy_kernel(const float* __restrict__ xin)
{
    int i = blockIdx.x * blockDim.x + threadIdx.x;
    if (i < NN * 3) g_x[i] = xin[i];
}

__global__ void zero_kernel()
{
    int i = blockIdx.x * blockDim.x + threadIdx.x;
    if (i < NN * HH / 4) ((float4*)g_m)[i] = make_float4(0.f, 0.f, 0.f, 0.f);
    if (i < NN * 3 / 4) ((float4*)g_xacc)[i] = make_float4(0.f, 0.f, 0.f, 0.f);
}

extern "C" void kernel_launch(void* const* d_in, const int* in_sizes, int n_in,
                              void* d_out, int out_size)
{
    const float* h_in  = (const float*)d_in[0];
    const float* x_in  = (const float*)d_in[1];
    const int*   ei    = (const int*)d_in[2];
    const float* emb_W = (const float*)d_in[3];
    const float* emb_b = (const float*)d_in[4];
    const float* eW1   = (const float*)d_in[5];
    const float* eb1   = (const float*)d_in[6];
    const float* eW2   = (const float*)d_in[7];
    const float* eb2   = (const float*)d_in[8];
    const float* nW1   = (const float*)d_in[9];
    const float* nb1   = (const float*)d_in[10];
    const float* nW2   = (const float*)d_in[11];
    const float* nb2   = (const float*)d_in[12];
    const float* cW1   = (const float*)d_in[13];
    const float* cb1   = (const float*)d_in[14];
    const float* cW2   = (const float*)d_in[15];
    const float* cb2   = (const float*)d_in[16];
    float* out = (float*)d_out;

    cudaFuncSetAttribute(edge_kernel, cudaFuncAttributeMaxDynamicSharedMemorySize, EDGE_SMEM_BYTES);
    cudaFuncSetAttribute(node_kernel, cudaFuncAttributeMaxDynamicSharedMemorySize, NODE_SMEM_BYTES);
    cudaFuncSetAttribute(proj_kernel, cudaFuncAttributeMaxDynamicSharedMemorySize, PROJ_SMEM_BYTES);

    xcopy_kernel<<<(NN * 3 + 255) / 256, 256>>>(x_in);
    embed_kernel<<<(NN * HH + 255) / 256, 256>>>(h_in, emb_W, emb_b);
    prep_kernel<<<(7 * 8192 + 255) / 256, 256>>>(eW1, eW2, cW1, nW1, nW2);
    compose_kernel<<<(32768 + 512 + NN + 255) / 256, 256>>>(eW2, cW1, eb2, cb1);
    deg_kernel<<<(EE + 255) / 256, 256>>>(ei);

    const int PB = (NN + TN - 1) / TN;
    for (int l = 0; l < 2; l++) {
        zero_kernel<<<(NN * HH / 4 + 255) / 256, 256>>>();
        proj_kernel<<<PB, NT, PROJ_SMEM_BYTES>>>();
        edge_kernel<<<EE / TE, NT, EDGE_SMEM_BYTES>>>(ei, eb1, cW2, cb2, eW1);
        bool fin = (l == 1);
        node_kernel<<<PB, NT, NODE_SMEM_BYTES>>>(
            nb1, nb2, eb2,
            fin ? out : (float*)nullptr,
            fin ? out + (size_t)NN * HH : (float*)nullptr);
    }
}